// round 10
// baseline (speedup 1.0000x reference)
#include <cuda_runtime.h>
#include <math.h>

// Batched SPD projection: per 64x64 real matrix A,
//   A = Q T Q^H (Hessenberg + complex single-shift QR),
//   chase: warp0 = left applies + Q[0:32), warp1 = right applies + Q[32:64),
//          warp2-lane0 = corner with register-carried window, publishes (c,s)
//          one step ahead. One __syncthreads per chase step, plus ONE barrier
//          per sweep separating the redundant deflation/shift reads from the
//          chase's first writes (the R8 race).
//   F = f(T) by Parlett (packed in lower triangle of H), M = Q F Q^H,
//   out = 0.5*(Re(M) + Re(M)^T).

#define N 64
#define LDH 65
#define ULPF 1.1920929e-7f
#define MAXSWEEPS 1920
#define NT 96

__device__ __forceinline__ float2 cadd(float2 a, float2 b){ return make_float2(a.x+b.x, a.y+b.y); }
__device__ __forceinline__ float2 csub(float2 a, float2 b){ return make_float2(a.x-b.x, a.y-b.y); }
__device__ __forceinline__ float2 cmulc(float2 a, float2 b){ return make_float2(a.x*b.x-a.y*b.y, a.x*b.y+a.y*b.x); }
__device__ __forceinline__ float cabs1(float2 a){ return fabsf(a.x)+fabsf(a.y); }
__device__ __forceinline__ float cabs2f(float2 a){ return a.x*a.x+a.y*a.y; }

// left Givens on (row k, row k+1):  a' = c*a + s*b ; b' = c*b - conj(s)*a
__device__ __forceinline__ void rotL(float2& a, float2& b, float c, float2 s){
    float2 na = make_float2(c*a.x + s.x*b.x - s.y*b.y, c*a.y + s.x*b.y + s.y*b.x);
    float2 nb = make_float2(c*b.x - (s.x*a.x + s.y*a.y), c*b.y - (s.x*a.y - s.y*a.x));
    a = na; b = nb;
}
// right Givens on (col k, col k+1): a' = c*a + conj(s)*b ; b' = c*b - s*a
__device__ __forceinline__ void rotR(float2& a, float2& b, float c, float2 s){
    float2 na = make_float2(c*a.x + s.x*b.x + s.y*b.y, c*a.y + s.x*b.y - s.y*b.x);
    float2 nb = make_float2(c*b.x - (s.x*a.x - s.y*a.y), c*b.y - (s.x*a.y + s.y*a.x));
    a = na; b = nb;
}

__device__ __forceinline__ void genrot(float2 f, float2 g, float& c, float2& s, float2& r){
    float ag = cabs2f(g), af = cabs2f(f);
    if (ag == 0.f) {
        c = 1.f; s = make_float2(0.f, 0.f); r = f;
    } else if (af == 0.f) {
        float gn = sqrtf(ag), gi = 1.f / gn;
        c = 0.f; s = make_float2(g.x * gi, -g.y * gi); r = make_float2(gn, 0.f);
    } else {
        float irf = rsqrtf(af), ird = rsqrtf(af + ag);
        float fa = af * irf;                 // sqrt(af)
        c = fa * ird;
        float sc = irf * ird;
        s = make_float2((f.x * g.x + f.y * g.y) * sc,
                        (f.y * g.x - f.x * g.y) * sc);   // (f/|f|)*conj(g)/d
        float rs = (af + ag) * ird * irf;    // sqrt(af+ag)/sqrt(af)
        r = make_float2(f.x * rs, f.y * rs);
    }
}

__global__ void __launch_bounds__(NT, 3)
spd_project_kernel(const float* __restrict__ X, float* __restrict__ OUT, int nmat)
{
    extern __shared__ float2 sm[];
    float2* H = sm;              // Hessenberg -> T (upper); F packed strict-lower; later G; Re(M) in .x
    float2* Q = sm + N * LDH;

    __shared__ float  s_red[3];
    __shared__ float  s_v[N];
    __shared__ float  s_fd[N];
    __shared__ float4 s_cs[2];   // double-buffered (c, s.x, s.y) mailbox

    const int tid = threadIdx.x;
    const int warp = tid >> 5;
    const int lane = tid & 31;
    const int g = blockIdx.x;
    if (g >= nmat) return;
    const float* A = X + (size_t)g * (N * N);
    float* Og = OUT + (size_t)g * (N * N);

    // ---------------- load A, Q = I ----------------
    for (int idx = tid; idx < N * N; idx += NT) {
        int i = idx >> 6, j = idx & 63;
        H[i * LDH + j] = make_float2(A[idx], 0.f);
        Q[i * LDH + j] = make_float2((i == j) ? 1.f : 0.f, 0.f);
    }
    __syncthreads();

    // ---------------- Hessenberg reduction (real; .y stays 0) ----------------
    for (int k = 0; k < N - 2; k++) {
        const int m = N - 1 - k;
        float t = 0.f;
        { int row = k + 2 + tid; if (row < N) { float h = H[row * LDH + k].x; t = h * h; } }
        #pragma unroll
        for (int off = 16; off >= 1; off >>= 1) t += __shfl_xor_sync(0xffffffffu, t, off);
        if (lane == 0) s_red[warp] = t;
        __syncthreads();
        const float sigma = s_red[0] + s_red[1] + s_red[2];
        if (sigma > 0.f) {   // uniform across threads
            float x0 = H[(k + 1) * LDH + k].x;
            float mu = sqrtf(x0 * x0 + sigma);
            float v0 = (x0 <= 0.f) ? (x0 - mu) : (-sigma / (x0 + mu));
            float beta = 2.f * v0 * v0 / (sigma + v0 * v0);
            float inv_v0 = 1.f / v0;
            if (tid < m) s_v[tid] = (tid == 0) ? 1.f : H[(k + 1 + tid) * LDH + k].x * inv_v0;
            __syncthreads();
            { int j = k + tid;
              if (j < N) {
                  float w = 0.f;
                  for (int i = 0; i < m; i++) w += s_v[i] * H[(k + 1 + i) * LDH + j].x;
                  w *= beta;
                  for (int i = 0; i < m; i++) H[(k + 1 + i) * LDH + j].x -= s_v[i] * w;
              } }
            __syncthreads();
            if (tid < N) {
              int i = tid;
              float w = 0.f, wq = 0.f;
              for (int l = 0; l < m; l++) w += H[i * LDH + k + 1 + l].x * s_v[l];
              w *= beta;
              for (int l = 0; l < m; l++) H[i * LDH + k + 1 + l].x -= w * s_v[l];
              for (int l = 0; l < m; l++) wq += Q[i * LDH + k + 1 + l].x * s_v[l];
              wq *= beta;
              for (int l = 0; l < m; l++) Q[i * LDH + k + 1 + l].x -= wq * s_v[l];
              if (i >= k + 2) H[i * LDH + k].x = 0.f;
            }
            __syncthreads();
        } else {
            __syncthreads();
        }
    }

    // ---------------- complex single-shift QR; control redundant on all threads ----------------
    int its = 0, totit = 0, hi = N - 1;
    while (true) {
        // deflation scan (redundant; benign same-value write races)
        while (hi > 0) {
            float sub = cabs1(H[hi * LDH + hi - 1]);
            float dd = cabs1(H[(hi - 1) * LDH + hi - 1]) + cabs1(H[hi * LDH + hi]);
            if (sub <= ULPF * dd + 1e-30f) {
                H[hi * LDH + hi - 1] = make_float2(0.f, 0.f);
                hi--; its = 0;
            } else break;
        }
        if (hi == 0 || totit >= MAXSWEEPS) break;
        totit++; its++;
        int lo = hi;
        while (lo > 0) {
            float sub = cabs1(H[lo * LDH + lo - 1]);
            float dd = cabs1(H[(lo - 1) * LDH + lo - 1]) + cabs1(H[lo * LDH + lo]);
            if (sub <= ULPF * dd + 1e-30f) {
                H[lo * LDH + lo - 1] = make_float2(0.f, 0.f);
                break;
            }
            lo--;
        }
        float2 sig;
        if ((its % 10) == 0) {   // exceptional shift
            sig = H[hi * LDH + hi];
            sig.x += 0.75f * cabs1(H[hi * LDH + hi - 1]);
        } else {                 // Wilkinson shift from trailing 2x2
            float2 a = H[(hi - 1) * LDH + hi - 1], b = H[(hi - 1) * LDH + hi];
            float2 cc2 = H[hi * LDH + hi - 1],     d2 = H[hi * LDH + hi];
            float2 tr = make_float2(0.5f * (a.x + d2.x), 0.5f * (a.y + d2.y));
            float2 u = make_float2(0.5f * (a.x - d2.x), 0.5f * (a.y - d2.y));
            float2 disc = cadd(cmulc(u, u), cmulc(b, cc2));
            float mm = sqrtf(disc.x * disc.x + disc.y * disc.y);
            float re = sqrtf(fmaxf(0.5f * (mm + disc.x), 0.f));
            float im = sqrtf(fmaxf(0.5f * (mm - disc.x), 0.f));
            im = copysignf(im, disc.y);
            float2 sq = make_float2(re, im);
            float2 e1 = cadd(tr, sq), e2 = csub(tr, sq);
            sig = (cabs2f(csub(e1, d2)) < cabs2f(csub(e2, d2))) ? e1 : e2;
        }

        // initial rotation for k = lo: all threads compute redundantly
        float c; float2 s, r;
        {
            float2 f0 = csub(H[lo * LDH + lo], sig);
            float2 g0 = H[(lo + 1) * LDH + lo];
            genrot(f0, g0, c, s, r);
        }

        // corner primes its register window
        float2 p00, p01, p02, p10, p11, p12, b1;
        if (tid == 64) {
            p00 = H[lo * LDH + lo];       p01 = H[lo * LDH + lo + 1];
            p10 = H[(lo + 1) * LDH + lo]; p11 = H[(lo + 1) * LDH + lo + 1];
            bool c2 = (lo + 2 < N);
            p02 = c2 ? H[lo * LDH + lo + 2] : make_float2(0.f, 0.f);
            p12 = c2 ? H[(lo + 1) * LDH + lo + 2] : make_float2(0.f, 0.f);
            b1  = (lo + 2 <= hi) ? H[(lo + 2) * LDH + lo + 1] : make_float2(0.f, 0.f);
        }

        // CRITICAL: separate the redundant control-phase READS (deflation scan,
        // shift 2x2, genrot inputs, corner priming) from the chase's first
        // WRITES. Without this, a fast warp's step-lo writes race with slower
        // warps still reading those cells (the R8 bug).
        __syncthreads();

        for (int k = lo; k < hi; k++) {
            if (k > lo && tid < 64) {     // lanes fetch (c,s) published one step ago
                float4 v = s_cs[k & 1];
                c = v.x; s = make_float2(v.y, v.z);
            }
            if (warp == 0) {
                // left: rows k,k+1 ; cols k+3.. (corner owns col k+2)
                int j = k + 3 + lane;
                if (j < N) {
                    float2 a = H[k * LDH + j], b = H[(k + 1) * LDH + j];
                    rotL(a, b, c, s);
                    H[k * LDH + j] = a; H[(k + 1) * LDH + j] = b;
                }
                j += 32;
                if (j < N) {
                    float2 a = H[k * LDH + j], b = H[(k + 1) * LDH + j];
                    rotL(a, b, c, s);
                    H[k * LDH + j] = a; H[(k + 1) * LDH + j] = b;
                }
                // Q rows 0..31
                float2 qa = Q[lane * LDH + k], qb = Q[lane * LDH + k + 1];
                rotR(qa, qb, c, s);
                Q[lane * LDH + k] = qa; Q[lane * LDH + k + 1] = qb;
            } else if (warp == 1) {
                // right: rows 0..k-1 ; cols k,k+1
                int i = lane;
                if (i < k) {
                    float2 a = H[i * LDH + k], b = H[i * LDH + k + 1];
                    rotR(a, b, c, s);
                    H[i * LDH + k] = a; H[i * LDH + k + 1] = b;
                }
                i += 32;
                if (i < k) {
                    float2 a = H[i * LDH + k], b = H[i * LDH + k + 1];
                    rotR(a, b, c, s);
                    H[i * LDH + k] = a; H[i * LDH + k + 1] = b;
                }
                // Q rows 32..63
                int qi = lane + 32;
                float2 qa = Q[qi * LDH + k], qb = Q[qi * LDH + k + 1];
                rotR(qa, qb, c, s);
                Q[qi * LDH + k] = qa; Q[qi * LDH + k + 1] = qb;
            } else if (lane == 0) {
                // corner: register-carried window
                rotL(p00, p10, c, s);
                rotL(p01, p11, c, s);
                bool hascol2 = (k + 2 < N);
                if (hascol2) rotL(p02, p12, c, s);
                float2 bulge = make_float2(0.f, 0.f), b1c = make_float2(0.f, 0.f);
                bool hasbulge = (k + 2 <= hi);
                if (hasbulge) {
                    bulge = make_float2(s.x * b1.x + s.y * b1.y, s.x * b1.y - s.y * b1.x); // conj(s)*b1
                    b1c = make_float2(c * b1.x, c * b1.y);
                }
                rotR(p00, p01, c, s);
                rotR(p10, p11, c, s);
                if (k > lo) H[k * LDH + k - 1] = r;
                H[k * LDH + k] = p00;
                H[k * LDH + k + 1] = p01;
                if (hascol2) H[k * LDH + k + 2] = p02;
                H[(k + 1) * LDH + k] = p10;
                if (hasbulge) {
                    H[(k + 2) * LDH + k] = bulge;
                    H[(k + 2) * LDH + k + 1] = b1c;
                }
                if (k + 1 < hi) {
                    genrot(p10, bulge, c, s, r);             // rotation for step k+1
                    s_cs[(k + 1) & 1] = make_float4(c, s.x, s.y, 0.f);
                    // shift window; cells untouched by this step's rotations load now
                    p00 = p11; p01 = p12; p10 = b1c;
                    p11 = H[(k + 2) * LDH + (k + 2)];
                    p12 = (k + 3 < N) ? H[(k + 2) * LDH + (k + 3)] : make_float2(0.f, 0.f);
                    b1  = (k + 3 <= hi) ? H[(k + 3) * LDH + (k + 2)] : make_float2(0.f, 0.f);
                } else {
                    H[(k + 1) * LDH + (k + 1)] = p11;        // finalize row hi
                    if (hascol2) H[(k + 1) * LDH + (k + 2)] = p12;
                }
            }
            __syncthreads();
            if (tid == 64 && k + 1 < hi) {   // lane-written entry for the next window
                p02 = (k + 3 < N) ? H[(k + 1) * LDH + (k + 3)] : make_float2(0.f, 0.f);
            }
        }
    }
    __syncthreads();

    // ---------------- lam = |w| + eps*min|w| ----------------
    {
        float a = 0.f;
        if (tid < N) { float2 w = H[tid * LDH + tid]; a = sqrtf(cabs2f(w)); }
        float t = (tid < N) ? a : 3.4e38f;
        #pragma unroll
        for (int off = 16; off >= 1; off >>= 1) t = fminf(t, __shfl_xor_sync(0xffffffffu, t, off));
        if (tid < N && lane == 0) s_red[warp] = t;
        __syncthreads();
        float amin = fminf(s_red[0], s_red[1]);
        if (tid < N) s_fd[tid] = a + 1e-6f * amin;
        __syncthreads();
    }

    // ---------------- F = f(T) via Parlett; F[i][j] (i<j) stored at H[j][i] ----------------
    for (int p = 1; p < N; p++) {
        int i = tid, j = i + p;
        if (j < N) {
            float2 Tij = H[i * LDH + j];
            float fdiff = s_fd[i] - s_fd[j];
            float2 num = make_float2(Tij.x * fdiff, Tij.y * fdiff);
            for (int kk = i + 1; kk < j; kk++) {
                float2 Fik = H[kk * LDH + i];
                float2 Tkj = H[kk * LDH + j];
                float2 Tik = H[i * LDH + kk];
                float2 Fkj = H[j * LDH + kk];
                num.x += (Fik.x * Tkj.x - Fik.y * Tkj.y) - (Tik.x * Fkj.x - Tik.y * Fkj.y);
                num.y += (Fik.x * Tkj.y + Fik.y * Tkj.x) - (Tik.x * Fkj.y + Tik.y * Fkj.x);
            }
            float2 den = csub(H[i * LDH + i], H[j * LDH + j]);
            float dd = fmaxf(cabs2f(den), 1e-30f);
            H[j * LDH + i] = make_float2((num.x * den.x + num.y * den.y) / dd,
                                         (num.y * den.x - num.x * den.y) / dd);
        }
        __syncthreads();
    }

    // ---------------- G = Q * F  (stage row in registers, then overwrite H) ----------------
    {
        float2 acc[N];
        if (tid < N) {
            const int i = tid;
            for (int j = 0; j < N; j++) {
                float2 qd = Q[i * LDH + j];
                float2 a = make_float2(qd.x * s_fd[j], qd.y * s_fd[j]);
                for (int kk = 0; kk < j; kk++) {
                    float2 qv = Q[i * LDH + kk];
                    float2 fv = H[j * LDH + kk];   // F[kk][j] packed
                    a.x += qv.x * fv.x - qv.y * fv.y;
                    a.y += qv.x * fv.y + qv.y * fv.x;
                }
                acc[j] = a;
            }
        }
        __syncthreads();
        if (tid < N) {
            for (int j = 0; j < N; j++) H[tid * LDH + j] = acc[j];
        }
    }
    __syncthreads();

    // ---------------- Re(M) = Re(G * Q^H) into H[i][*].x ----------------
    {
        float accr[N];
        if (tid < N) {
            const int i = tid;
            for (int j = 0; j < N; j++) {
                float a = 0.f;
                for (int kk = 0; kk < N; kk++) {
                    float2 gv = H[i * LDH + kk], qv = Q[j * LDH + kk];
                    a += gv.x * qv.x + gv.y * qv.y;   // Re(g * conj(q))
                }
                accr[j] = a;
            }
            for (int j = 0; j < N; j++) H[i * LDH + j].x = accr[j];
        }
    }
    __syncthreads();

    // ---------------- out = 0.5*(Re(M) + Re(M)^T) ----------------
    for (int idx = tid; idx < N * N; idx += NT) {
        int i = idx >> 6, j = idx & 63;
        Og[idx] = 0.5f * (H[i * LDH + j].x + H[j * LDH + i].x);
    }
}

extern "C" void kernel_launch(void* const* d_in, const int* in_sizes, int n_in,
                              void* d_out, int out_size) {
    const float* x = (const float*)d_in[0];
    float* out = (float*)d_out;
    int nmat = in_sizes[0] / (N * N);
    size_t smem = 2 * N * LDH * sizeof(float2);  // 66,560 bytes -> 3 blocks/SM
    cudaFuncSetAttribute(spd_project_kernel,
                         cudaFuncAttributeMaxDynamicSharedMemorySize, (int)smem);
    spd_project_kernel<<<nmat, NT, smem>>>(x, out, nmat);
}

// round 11
// speedup vs baseline: 1.6822x; 1.6822x over previous
#include <cuda_runtime.h>
#include <math.h>

#define N 64
#define LDH 65
#define ULPF 1.1920929e-7f
#define MAXSW 960
#define NT 96

__device__ __forceinline__ float guard(float d){ return (fabsf(d)<1e-25f)?copysignf(1e-25f,d):d; }
__device__ __forceinline__ void gen3(float x,float y,float z,float&tau,float&v1,float&v2){
    float ssq=y*y+z*z;
    if(ssq==0.f){tau=0.f;v1=0.f;v2=0.f;return;}
    float nrm=sqrtf(x*x+ssq);
    float beta=(x>=0.f)?-nrm:nrm;
    tau=(beta-x)/beta; float inv=1.f/(x-beta);
    v1=y*inv; v2=z*inv;
}
__device__ __forceinline__ void gen2(float x,float y,float&tau,float&v1){
    if(y==0.f){tau=0.f;v1=0.f;return;}
    float nrm=sqrtf(x*x+y*y);
    float beta=(x>=0.f)?-nrm:nrm;
    tau=(beta-x)/beta; v1=y/(x-beta);
}

__global__ void __launch_bounds__(NT, 6)
spd_project_kernel(const float* __restrict__ X, float* __restrict__ OUT, int nmat)
{
    extern __shared__ float sm[];
    float* H = sm;            // Hessenberg -> T; F packed strictly-lower; later G
    float* Q = sm + N * LDH;

    __shared__ float  s_red[3];
    __shared__ float  s_v[N];
    __shared__ int    s_bs[N], s_fbi[N];     // per-col block start / block index
    __shared__ int    s_cb[N], s_bsz[N];     // per-block start / size
    __shared__ float  s_f2[N][4];            // F_II per block
    __shared__ int    s_nb;
    __shared__ float  s_amin;
    __shared__ float4 s_mb[2];               // (tau,v1,v2) mailbox

    const int tid = threadIdx.x, warp = tid >> 5, lane = tid & 31;
    const int g = blockIdx.x;
    if (g >= nmat) return;
    const float* A = X + (size_t)g * (N * N);
    float* Og = OUT + (size_t)g * (N * N);

    for (int idx = tid; idx < N * N; idx += NT) {
        int i = idx >> 6, j = idx & 63;
        H[i * LDH + j] = A[idx];
        Q[i * LDH + j] = (i == j) ? 1.f : 0.f;
    }
    __syncthreads();

    // ---------- Hessenberg ----------
    for (int k = 0; k < N - 2; k++) {
        const int m = N - 1 - k;
        float t = 0.f;
        { int row = k + 2 + tid; if (row < N) { float h = H[row * LDH + k]; t = h * h; } }
        #pragma unroll
        for (int off = 16; off >= 1; off >>= 1) t += __shfl_xor_sync(0xffffffffu, t, off);
        if (lane == 0) s_red[warp] = t;
        __syncthreads();
        const float sigma = s_red[0] + s_red[1] + s_red[2];
        if (sigma > 0.f) {
            float x0 = H[(k + 1) * LDH + k];
            float mu = sqrtf(x0 * x0 + sigma);
            float v0 = (x0 <= 0.f) ? (x0 - mu) : (-sigma / (x0 + mu));
            float beta = 2.f * v0 * v0 / (sigma + v0 * v0);
            float iv0 = 1.f / v0;
            if (tid < m) s_v[tid] = (tid == 0) ? 1.f : H[(k + 1 + tid) * LDH + k] * iv0;
            __syncthreads();
            { int j = k + tid;
              if (j < N) {
                  float w = 0.f;
                  for (int i = 0; i < m; i++) w += s_v[i] * H[(k + 1 + i) * LDH + j];
                  w *= beta;
                  for (int i = 0; i < m; i++) H[(k + 1 + i) * LDH + j] -= s_v[i] * w;
              } }
            __syncthreads();
            if (tid < N) {
              int i = tid;
              float w = 0.f, wq = 0.f;
              for (int l = 0; l < m; l++) w += H[i * LDH + k + 1 + l] * s_v[l];
              w *= beta;
              for (int l = 0; l < m; l++) H[i * LDH + k + 1 + l] -= w * s_v[l];
              for (int l = 0; l < m; l++) wq += Q[i * LDH + k + 1 + l] * s_v[l];
              wq *= beta;
              for (int l = 0; l < m; l++) Q[i * LDH + k + 1 + l] -= wq * s_v[l];
              if (i >= k + 2) H[i * LDH + k] = 0.f;
            }
            __syncthreads();
        } else __syncthreads();
    }

    // ---------- Francis double-shift QR (redundant control) ----------
    {
        int its = 0, tot = 0, hi = N - 1, lo = 0;
        while (true) {
            bool again = true;
            while (again && hi > 0) {
                again = false; lo = 0;
                for (int m = hi; m >= 1; m--) {
                    float sub = fabsf(H[m * LDH + m - 1]);
                    float dd = fabsf(H[(m - 1) * LDH + m - 1]) + fabsf(H[m * LDH + m]);
                    if (sub <= ULPF * dd + 1e-30f) { H[m * LDH + m - 1] = 0.f; lo = m; break; }
                }
                if (lo == hi)          { hi -= 1; its = 0; again = true; }
                else if (lo == hi - 1) { hi -= 2; its = 0; again = true; }
            }
            if (hi <= 0 || tot >= MAXSW) break;
            tot++; its++;
            float t, d;
            if (its % 10 == 0) {
                float s2 = fabsf(H[hi * LDH + hi - 1]) + fabsf(H[(hi - 1) * LDH + hi - 2]);
                float h11 = 0.75f * s2 + H[hi * LDH + hi];
                t = 2.f * h11; d = h11 * h11 + 0.4375f * s2 * s2;
            } else {
                t = H[(hi - 1) * LDH + hi - 1] + H[hi * LDH + hi];
                d = H[(hi - 1) * LDH + hi - 1] * H[hi * LDH + hi]
                  - H[(hi - 1) * LDH + hi] * H[hi * LDH + hi - 1];
            }
            float h00 = H[lo * LDH + lo],       h01 = H[lo * LDH + lo + 1];
            float h10 = H[(lo + 1) * LDH + lo], h11 = H[(lo + 1) * LDH + lo + 1];
            float h21 = H[(lo + 2) * LDH + lo + 1];
            float tau, v1, v2;
            gen3(h00 * h00 + h01 * h10 - t * h00 + d, h10 * (h00 + h11 - t), h21 * h10, tau, v1, v2);
            __syncthreads();   // control reads before chase writes

            for (int k = lo; k < hi; k++) {
                bool last = (k == hi - 1);
                if (k > lo) { float4 mb = s_mb[k & 1]; tau = mb.x; v1 = mb.y; v2 = mb.z; }
                if (warp == 0) {
                    int jb = last ? (k + 2) : (k + 3);
                    #pragma unroll
                    for (int rep = 0; rep < 2; rep++) {
                        int j = jb + lane + rep * 32;
                        if (j < N) {
                            float a0 = H[k * LDH + j], a1 = H[(k + 1) * LDH + j];
                            if (!last) {
                                float a2 = H[(k + 2) * LDH + j];
                                float s0 = tau * (a0 + v1 * a1 + v2 * a2);
                                H[k * LDH + j] = a0 - s0; H[(k + 1) * LDH + j] = a1 - v1 * s0;
                                H[(k + 2) * LDH + j] = a2 - v2 * s0;
                            } else {
                                float s0 = tau * (a0 + v1 * a1);
                                H[k * LDH + j] = a0 - s0; H[(k + 1) * LDH + j] = a1 - v1 * s0;
                            }
                        }
                    }
                } else if (warp == 1) {
                    if (lane < 31) {
                        #pragma unroll
                        for (int rep = 0; rep < 2; rep++) {
                            int i = lane + rep * 31;
                            if (i < k) {
                                float a0 = H[i * LDH + k], a1 = H[i * LDH + k + 1];
                                if (!last) {
                                    float a2 = H[i * LDH + k + 2];
                                    float s0 = tau * (a0 + v1 * a1 + v2 * a2);
                                    H[i * LDH + k] = a0 - s0; H[i * LDH + k + 1] = a1 - v1 * s0;
                                    H[i * LDH + k + 2] = a2 - v2 * s0;
                                } else {
                                    float s0 = tau * (a0 + v1 * a1);
                                    H[i * LDH + k] = a0 - s0; H[i * LDH + k + 1] = a1 - v1 * s0;
                                }
                            }
                        }
                    } else {
                        // ---- owner: col k-1 annihilation + window + next Householder ----
                        if (!last) {
                            if (k > lo) {
                                float x0 = H[k*LDH+k-1], y0 = H[(k+1)*LDH+k-1], z0 = H[(k+2)*LDH+k-1];
                                H[k*LDH+k-1] = x0 - tau * (x0 + v1*y0 + v2*z0);
                                H[(k+1)*LDH+k-1] = 0.f; H[(k+2)*LDH+k-1] = 0.f;
                            }
                            int rmax = (k + 3 <= hi) ? 3 : 2;
                            float w[4][3];
                            for (int r = 0; r <= rmax; r++)
                                for (int c2 = 0; c2 < 3; c2++) w[r][c2] = H[(k + r) * LDH + k + c2];
                            for (int c2 = 0; c2 < 3; c2++) {
                                float s0 = tau * (w[0][c2] + v1 * w[1][c2] + v2 * w[2][c2]);
                                w[0][c2] -= s0; w[1][c2] -= v1 * s0; w[2][c2] -= v2 * s0;
                            }
                            for (int r = 0; r <= rmax; r++) {
                                float s0 = tau * (w[r][0] + v1 * w[r][1] + v2 * w[r][2]);
                                w[r][0] -= s0; w[r][1] -= v1 * s0; w[r][2] -= v2 * s0;
                            }
                            for (int r = 0; r <= rmax; r++)
                                for (int c2 = 0; c2 < 3; c2++) H[(k + r) * LDH + k + c2] = w[r][c2];
                            float nt, nv1, nv2 = 0.f;
                            if (k + 1 == hi - 1) { gen2(w[1][0], w[2][0], nt, nv1); }
                            else                 { gen3(w[1][0], w[2][0], w[3][0], nt, nv1, nv2); }
                            s_mb[(k + 1) & 1] = make_float4(nt, nv1, nv2, 0.f);
                        } else {
                            float x0 = H[k*LDH+k-1], y0 = H[(k+1)*LDH+k-1];
                            H[k*LDH+k-1] = x0 - tau * (x0 + v1*y0);
                            H[(k+1)*LDH+k-1] = 0.f;
                            float w00=H[k*LDH+k], w01=H[k*LDH+k+1], w10=H[(k+1)*LDH+k], w11=H[(k+1)*LDH+k+1];
                            { float s0=tau*(w00+v1*w10); w00-=s0; w10-=v1*s0; }
                            { float s0=tau*(w01+v1*w11); w01-=s0; w11-=v1*s0; }
                            { float s0=tau*(w00+v1*w01); w00-=s0; w01-=v1*s0; }
                            { float s0=tau*(w10+v1*w11); w10-=s0; w11-=v1*s0; }
                            H[k*LDH+k]=w00; H[k*LDH+k+1]=w01; H[(k+1)*LDH+k]=w10; H[(k+1)*LDH+k+1]=w11;
                        }
                    }
                } else {
                    #pragma unroll
                    for (int rep = 0; rep < 2; rep++) {
                        int i = lane + rep * 32;
                        float q0 = Q[i * LDH + k], q1 = Q[i * LDH + k + 1];
                        if (!last) {
                            float q2 = Q[i * LDH + k + 2];
                            float s0 = tau * (q0 + v1 * q1 + v2 * q2);
                            Q[i*LDH+k]=q0-s0; Q[i*LDH+k+1]=q1-v1*s0; Q[i*LDH+k+2]=q2-v2*s0;
                        } else {
                            float s0 = tau * (q0 + v1 * q1);
                            Q[i*LDH+k]=q0-s0; Q[i*LDH+k+1]=q1-v1*s0;
                        }
                    }
                }
                __syncthreads();
            }
        }
    }
    __syncthreads();

    // ---------- identify diagonal blocks ----------
    if (tid == 0) {
        int b = 0, i = 0;
        while (i < N) {
            int sz = (i < N - 1 && H[(i + 1) * LDH + i] != 0.f) ? 2 : 1;
            s_cb[b] = i; s_bsz[b] = sz;
            s_bs[i] = i; s_fbi[i] = b;
            if (sz == 2) { s_bs[i + 1] = i; s_fbi[i + 1] = b; }
            i += sz; b++;
        }
        s_nb = b;
    }
    __syncthreads();
    const int nb = s_nb;

    // ---------- amin over eigenvalue magnitudes ----------
    {
        float em = 3.4e38f;
        if (tid < nb) {
            int i = s_cb[tid];
            if (s_bsz[tid] == 1) em = fabsf(H[i * LDH + i]);
            else {
                float a=H[i*LDH+i], b=H[i*LDH+i+1], c=H[(i+1)*LDH+i], dd=H[(i+1)*LDH+i+1];
                float md=0.5f*(a-dd), disc=md*md+b*c;
                if (disc < 0.f) em = sqrtf(fmaxf(a*dd - b*c, 0.f));
                else {
                    float sq=sqrtf(disc), m2=0.5f*(a+dd);
                    em = fminf(fabsf(m2+sq), fabsf(m2-sq));
                }
            }
        }
        #pragma unroll
        for (int off = 16; off >= 1; off >>= 1) em = fminf(em, __shfl_xor_sync(0xffffffffu, em, off));
        if (lane == 0) s_red[warp] = em;
        __syncthreads();
        if (tid == 0) s_amin = fminf(s_red[0], fminf(s_red[1], s_red[2]));
        __syncthreads();
    }

    // ---------- per-block F_II ----------
    if (tid < nb) {
        int i = s_cb[tid];
        float e = 1e-6f * s_amin;
        if (s_bsz[tid] == 1) s_f2[tid][0] = fabsf(H[i * LDH + i]) + e;
        else {
            float a=H[i*LDH+i], b=H[i*LDH+i+1], c=H[(i+1)*LDH+i], dd=H[(i+1)*LDH+i+1];
            float md=0.5f*(a-dd), disc=md*md+b*c, m2=0.5f*(a+dd);
            if (disc < 0.f) {
                float cc = sqrtf(fmaxf(a*dd - b*c, 0.f)) + e;
                s_f2[tid][0]=cc; s_f2[tid][1]=0.f; s_f2[tid][2]=0.f; s_f2[tid][3]=cc;
            } else {
                float sq=sqrtf(disc), l1=m2+sq, l2=m2-sq;
                float f1=fabsf(l1)+e, f2=fabsf(l2)+e, al, be;
                if (fabsf(l1-l2) > 1e-5f*(fabsf(l1)+fabsf(l2)) + 1e-30f) {
                    float idl = 1.f/(l1-l2);
                    al=(f1-f2)*idl; be=(f2*l1-f1*l2)*idl;
                } else { al=(l1>=0.f)?1.f:-1.f; be=f1-al*l1; }
                s_f2[tid][0]=al*a+be; s_f2[tid][1]=al*b; s_f2[tid][2]=al*c; s_f2[tid][3]=al*dd+be;
            }
        }
    }
    __syncthreads();

    // ---------- block Parlett: F_IJ packed at H[(iJ+c)*LDH + iI+r] ----------
    for (int pd = 1; pd < nb; pd++) {
        int I = tid, J = I + pd;
        if (J < nb) {
            int nI=s_bsz[I], nJ=s_bsz[J], iI=s_cb[I], iJ=s_cb[J];
            float TIJ[4], Rv[4]={0,0,0,0};
            for (int r=0;r<nI;r++) for (int c=0;c<nJ;c++) TIJ[r*2+c]=H[(iI+r)*LDH+iJ+c];
            for (int r=0;r<nI;r++) for (int c=0;c<nJ;c++) {
                float acc=0.f;
                for (int q=0;q<nI;q++) acc += s_f2[I][r*2+q]*TIJ[q*2+c];
                for (int q=0;q<nJ;q++) acc -= TIJ[r*2+q]*s_f2[J][q*2+c];
                Rv[r*2+c]=acc;
            }
            for (int K=I+1;K<J;K++) {
                int nK=s_bsz[K], iK=s_cb[K];
                for (int r=0;r<nI;r++) for (int c=0;c<nJ;c++) {
                    float acc=Rv[r*2+c];
                    for (int q=0;q<nK;q++)
                        acc += H[(iK+q)*LDH+iI+r]*H[(iK+q)*LDH+iJ+c]
                             - H[(iI+r)*LDH+iK+q]*H[(iJ+c)*LDH+iK+q];
                    Rv[r*2+c]=acc;
                }
            }
            float TII[4], TJJ[4];
            for (int r=0;r<nI;r++) for (int c=0;c<nI;c++) TII[r*2+c]=H[(iI+r)*LDH+iI+c];
            for (int r=0;r<nJ;r++) for (int c=0;c<nJ;c++) TJJ[r*2+c]=H[(iJ+r)*LDH+iJ+c];
            int n = nI * nJ;
            float K4[16], Xv[4];
            for (int c=0;c<nJ;c++) for (int r=0;r<nI;r++) {
                int row = r + nI*c;
                for (int c2=0;c2<nJ;c2++) for (int r2=0;r2<nI;r2++) {
                    int col = r2 + nI*c2;
                    float val = 0.f;
                    if (c == c2) val += TII[r*2+r2];
                    if (r == r2) val -= TJJ[c2*2+c];
                    K4[row*4+col] = val;
                }
                Xv[row] = Rv[r*2+c];
            }
            for (int p=0;p<n;p++) {
                int pv=p; float mx=fabsf(K4[p*4+p]);
                for (int q=p+1;q<n;q++){ float v=fabsf(K4[q*4+p]); if(v>mx){mx=v;pv=q;} }
                if (pv!=p){ for(int q=p;q<n;q++){float tmp=K4[p*4+q];K4[p*4+q]=K4[pv*4+q];K4[pv*4+q]=tmp;}
                            float tmp=Xv[p];Xv[p]=Xv[pv];Xv[pv]=tmp; }
                float ip = 1.f / guard(K4[p*4+p]);
                for (int q=p+1;q<n;q++) {
                    float fc = K4[q*4+p]*ip;
                    for (int q3=p+1;q3<n;q3++) K4[q*4+q3]-=fc*K4[p*4+q3];
                    Xv[q]-=fc*Xv[p];
                }
            }
            for (int p=n-1;p>=0;p--) {
                float acc=Xv[p];
                for (int q=p+1;q<n;q++) acc-=K4[p*4+q]*Xv[q];
                Xv[p]=acc/guard(K4[p*4+p]);
            }
            for (int c=0;c<nJ;c++) for (int r=0;r<nI;r++) H[(iJ+c)*LDH+iI+r]=Xv[r+nI*c];
        }
        __syncthreads();
    }

    // ---------- G = Q * F (stage row in registers) ----------
    {
        float acc[N];
        if (tid < N) {
            int r = tid;
            for (int j = 0; j < N; j++) {
                int bsj = s_bs[j], b = s_fbi[j];
                float a = 0.f;
                for (int i2 = 0; i2 < bsj; i2++) a += Q[r*LDH+i2] * H[j*LDH+i2];
                if (s_bsz[b] == 1) a += Q[r*LDH+j] * s_f2[b][0];
                else {
                    int loc = j - bsj;
                    a += Q[r*LDH+bsj] * s_f2[b][loc] + Q[r*LDH+bsj+1] * s_f2[b][2+loc];
                }
                acc[j] = a;
            }
        }
        __syncthreads();
        if (tid < N) for (int j = 0; j < N; j++) H[tid*LDH+j] = acc[j];
    }
    __syncthreads();

    // ---------- M = G * Q^T into H (own row) ----------
    {
        float acc[N];
        if (tid < N) {
            int i = tid;
            for (int j = 0; j < N; j++) {
                float a = 0.f;
                for (int kk = 0; kk < N; kk++) a += H[i*LDH+kk] * Q[j*LDH+kk];
                acc[j] = a;
            }
            for (int j = 0; j < N; j++) H[i*LDH+j] = acc[j];
        }
    }
    __syncthreads();

    for (int idx = tid; idx < N * N; idx += NT) {
        int i = idx >> 6, j = idx & 63;
        Og[idx] = 0.5f * (H[i * LDH + j] + H[j * LDH + i]);
    }
}

extern "C" void kernel_launch(void* const* d_in, const int* in_sizes, int n_in,
                              void* d_out, int out_size) {
    const float* x = (const float*)d_in[0];
    float* out = (float*)d_out;
    int nmat = in_sizes[0] / (N * N);
    size_t smem = 2 * N * LDH * sizeof(float);   // 33,280 B -> 6 blocks/SM
    spd_project_kernel<<<nmat, NT, smem>>>(x, out, nmat);
}

// round 12
// speedup vs baseline: 1.9452x; 1.1564x over previous
#include <cuda_runtime.h>
#include <math.h>

#define N 64
#define LDH 65
#define ULPF 1.1920929e-7f
#define MAXSW 960
#define NT 128

__device__ __forceinline__ float guard(float d){ return (fabsf(d)<1e-25f)?copysignf(1e-25f,d):d; }
__device__ __forceinline__ void gen3(float x,float y,float z,float&tau,float&v1,float&v2,float&beta){
    float ssq=y*y+z*z;
    if(ssq==0.f){tau=0.f;v1=0.f;v2=0.f;beta=x;return;}
    float nrm=sqrtf(x*x+ssq);
    beta=(x>=0.f)?-nrm:nrm;
    tau=(beta-x)/beta; float inv=1.f/(x-beta);
    v1=y*inv; v2=z*inv;
}
__device__ __forceinline__ void gen2(float x,float y,float&tau,float&v1,float&beta){
    if(y==0.f){tau=0.f;v1=0.f;beta=x;return;}
    float nrm=sqrtf(x*x+y*y);
    beta=(x>=0.f)?-nrm:nrm;
    tau=(beta-x)/beta; v1=y/(x-beta);
}

__global__ void __launch_bounds__(NT, 6)
spd_project_kernel(const float* __restrict__ X, float* __restrict__ OUT, int nmat)
{
    extern __shared__ float sm[];
    float* H = sm;
    float* Q = sm + N * LDH;

    __shared__ float  s_red[4];
    __shared__ float  s_v[N];
    __shared__ int    s_bs[N], s_fbi[N];
    __shared__ int    s_cb[N], s_bsz[N];
    __shared__ float  s_f2[N][4];
    __shared__ int    s_nb;
    __shared__ float  s_amin;
    __shared__ float4 s_mb[2];

    const int tid = threadIdx.x, warp = tid >> 5, lane = tid & 31;
    const int g = blockIdx.x;
    if (g >= nmat) return;
    const float* A = X + (size_t)g * (N * N);
    float* Og = OUT + (size_t)g * (N * N);

    for (int idx = tid; idx < N * N; idx += NT) {
        int i = idx >> 6, j = idx & 63;
        H[i * LDH + j] = A[idx];
        Q[i * LDH + j] = (i == j) ? 1.f : 0.f;
    }
    __syncthreads();

    // ---------- Hessenberg ----------
    for (int k = 0; k < N - 2; k++) {
        const int m = N - 1 - k;
        float t = 0.f;
        { int row = k + 2 + tid; if (row < N) { float h = H[row * LDH + k]; t = h * h; } }
        #pragma unroll
        for (int off = 16; off >= 1; off >>= 1) t += __shfl_xor_sync(0xffffffffu, t, off);
        if (lane == 0) s_red[warp] = t;
        __syncthreads();
        const float sigma = s_red[0] + s_red[1] + s_red[2] + s_red[3];
        if (sigma > 0.f) {
            float x0 = H[(k + 1) * LDH + k];
            float mu = sqrtf(x0 * x0 + sigma);
            float v0 = (x0 <= 0.f) ? (x0 - mu) : (-sigma / (x0 + mu));
            float beta = 2.f * v0 * v0 / (sigma + v0 * v0);
            float iv0 = 1.f / v0;
            if (tid < m) s_v[tid] = (tid == 0) ? 1.f : H[(k + 1 + tid) * LDH + k] * iv0;
            __syncthreads();
            if (tid < 64) {           // left-apply on H columns
                int j = k + tid;
                if (j < N) {
                    float w = 0.f;
                    for (int i = 0; i < m; i++) w += s_v[i] * H[(k + 1 + i) * LDH + j];
                    w *= beta;
                    for (int i = 0; i < m; i++) H[(k + 1 + i) * LDH + j] -= s_v[i] * w;
                }
            } else {                  // right-apply on Q rows (independent of H-left)
                int i = tid - 64;
                float wq = 0.f;
                for (int l = 0; l < m; l++) wq += Q[i * LDH + k + 1 + l] * s_v[l];
                wq *= beta;
                for (int l = 0; l < m; l++) Q[i * LDH + k + 1 + l] -= wq * s_v[l];
            }
            __syncthreads();
            if (tid < N) {            // right-apply on H rows
              int i = tid;
              float w = 0.f;
              for (int l = 0; l < m; l++) w += H[i * LDH + k + 1 + l] * s_v[l];
              w *= beta;
              for (int l = 0; l < m; l++) H[i * LDH + k + 1 + l] -= w * s_v[l];
              if (i >= k + 2) H[i * LDH + k] = 0.f;
            }
            __syncthreads();
        } else __syncthreads();
    }

    // ---------- Francis double-shift QR ----------
    {
        int its = 0, tot = 0, hi = N - 1, lo = 0;
        float w[4][3];
        float tau, v1, v2, betac;
        while (true) {
            bool again = true;
            while (again && hi > 0) {
                again = false; lo = 0;
                for (int m = hi; m >= 1; m--) {
                    float sub = fabsf(H[m * LDH + m - 1]);
                    float dd = fabsf(H[(m - 1) * LDH + m - 1]) + fabsf(H[m * LDH + m]);
                    if (sub <= ULPF * dd + 1e-30f) { H[m * LDH + m - 1] = 0.f; lo = m; break; }
                }
                if (lo == hi)          { hi -= 1; its = 0; again = true; }
                else if (lo == hi - 1) { hi -= 2; its = 0; again = true; }
            }
            if (hi <= 0 || tot >= MAXSW) break;
            tot++; its++;
            float t, d;
            if (its % 10 == 0) {
                float s2 = fabsf(H[hi * LDH + hi - 1]) + fabsf(H[(hi - 1) * LDH + hi - 2]);
                float h11 = 0.75f * s2 + H[hi * LDH + hi];
                t = 2.f * h11; d = h11 * h11 + 0.4375f * s2 * s2;
            } else {
                t = H[(hi - 1) * LDH + hi - 1] + H[hi * LDH + hi];
                d = H[(hi - 1) * LDH + hi - 1] * H[hi * LDH + hi]
                  - H[(hi - 1) * LDH + hi] * H[hi * LDH + hi - 1];
            }
            float h00 = H[lo * LDH + lo],       h01 = H[lo * LDH + lo + 1];
            float h10 = H[(lo + 1) * LDH + lo], h11 = H[(lo + 1) * LDH + lo + 1];
            float h21 = H[(lo + 2) * LDH + lo + 1];
            gen3(h00*h00 + h01*h10 - t*h00 + d, h10*(h00 + h11 - t), h21*h10, tau, v1, v2, betac);

            if (tid == 96) {          // owner primes register window
                #pragma unroll
                for (int r = 0; r < 3; r++)
                    #pragma unroll
                    for (int c = 0; c < 3; c++) w[r][c] = H[(lo + r) * LDH + lo + c];
                bool r3 = (lo + 3 <= hi);
                #pragma unroll
                for (int c = 0; c < 3; c++) w[3][c] = r3 ? H[(lo + 3) * LDH + lo + c] : 0.f;
            }
            __syncthreads();          // control reads before chase writes

            for (int k = lo; k < hi; k++) {
                bool last = (k == hi - 1);
                if (k > lo && tid < 96) { float4 mb = s_mb[k & 1]; tau = mb.x; v1 = mb.y; v2 = mb.z; }
                if (warp == 0) {
                    int jb = last ? (k + 2) : (k + 3);
                    #pragma unroll
                    for (int rep = 0; rep < 2; rep++) {
                        int j = jb + lane + rep * 32;
                        if (j < N) {
                            float a0 = H[k * LDH + j], a1 = H[(k + 1) * LDH + j];
                            if (!last) {
                                float a2 = H[(k + 2) * LDH + j];
                                float s0 = tau * (a0 + v1 * a1 + v2 * a2);
                                H[k*LDH+j] = a0 - s0; H[(k+1)*LDH+j] = a1 - v1*s0; H[(k+2)*LDH+j] = a2 - v2*s0;
                            } else {
                                float s0 = tau * (a0 + v1 * a1);
                                H[k*LDH+j] = a0 - s0; H[(k+1)*LDH+j] = a1 - v1*s0;
                            }
                        }
                    }
                } else if (warp == 1) {
                    #pragma unroll
                    for (int rep = 0; rep < 2; rep++) {
                        int i = lane + rep * 32;
                        if (i < k) {
                            float a0 = H[i * LDH + k], a1 = H[i * LDH + k + 1];
                            if (!last) {
                                float a2 = H[i * LDH + k + 2];
                                float s0 = tau * (a0 + v1 * a1 + v2 * a2);
                                H[i*LDH+k] = a0 - s0; H[i*LDH+k+1] = a1 - v1*s0; H[i*LDH+k+2] = a2 - v2*s0;
                            } else {
                                float s0 = tau * (a0 + v1 * a1);
                                H[i*LDH+k] = a0 - s0; H[i*LDH+k+1] = a1 - v1*s0;
                            }
                        }
                    }
                } else if (warp == 2) {
                    #pragma unroll
                    for (int rep = 0; rep < 2; rep++) {
                        int i = lane + rep * 32;
                        float q0 = Q[i * LDH + k], q1 = Q[i * LDH + k + 1];
                        if (!last) {
                            float q2 = Q[i * LDH + k + 2];
                            float s0 = tau * (q0 + v1 * q1 + v2 * q2);
                            Q[i*LDH+k] = q0 - s0; Q[i*LDH+k+1] = q1 - v1*s0; Q[i*LDH+k+2] = q2 - v2*s0;
                        } else {
                            float s0 = tau * (q0 + v1 * q1);
                            Q[i*LDH+k] = q0 - s0; Q[i*LDH+k+1] = q1 - v1*s0;
                        }
                    }
                } else if (lane == 0) {   // owner (tid 96)
                    if (!last) {
                        if (k > lo) H[k * LDH + k - 1] = betac;
                        #pragma unroll
                        for (int c = 0; c < 3; c++) {
                            float s0 = tau * (w[0][c] + v1 * w[1][c] + v2 * w[2][c]);
                            w[0][c] -= s0; w[1][c] -= v1 * s0; w[2][c] -= v2 * s0;
                        }
                        #pragma unroll
                        for (int r = 0; r < 4; r++) {
                            float s0 = tau * (w[r][0] + v1 * w[r][1] + v2 * w[r][2]);
                            w[r][0] -= s0; w[r][1] -= v1 * s0; w[r][2] -= v2 * s0;
                        }
                        float tn, v1n, v2n = 0.f, bn;
                        if (k + 1 == hi - 1) { gen2(w[1][0], w[2][0], tn, v1n, bn); }
                        else                 { gen3(w[1][0], w[2][0], w[3][0], tn, v1n, v2n, bn); }
                        s_mb[(k + 1) & 1] = make_float4(tn, v1n, v2n, 0.f);
                        H[k*LDH+k] = w[0][0]; H[k*LDH+k+1] = w[0][1]; H[k*LDH+k+2] = w[0][2];
                        #pragma unroll
                        for (int r = 0; r < 3; r++) { w[r][0] = w[r+1][1]; w[r][1] = w[r+1][2]; }
                        w[3][0] = 0.f; w[3][1] = 0.f;
                        tau = tn; v1 = v1n; v2 = v2n; betac = bn;
                    } else {
                        H[k * LDH + k - 1] = betac;
                        float a0 = w[0][0], a1 = w[0][1], b0 = w[1][0], b1 = w[1][1];
                        { float s0 = tau * (a0 + v1 * b0); a0 -= s0; b0 -= v1 * s0; }
                        { float s0 = tau * (a1 + v1 * b1); a1 -= s0; b1 -= v1 * s0; }
                        { float s0 = tau * (a0 + v1 * a1); a0 -= s0; a1 -= v1 * s0; }
                        { float s0 = tau * (b0 + v1 * b1); b0 -= s0; b1 -= v1 * s0; }
                        H[k*LDH+k] = a0; H[k*LDH+k+1] = a1; H[(k+1)*LDH+k] = b0; H[(k+1)*LDH+k+1] = b1;
                    }
                }
                __syncthreads();
                if (tid == 96 && k + 1 < hi) {   // fresh col k+3 for next window
                    int c3 = k + 3;   // <= 64: pad column, safe
                    w[0][2] = H[(k + 1) * LDH + c3];
                    w[1][2] = (k + 2 <= hi) ? H[(k + 2) * LDH + c3] : 0.f;
                    w[2][2] = (k + 3 <= hi) ? H[(k + 3) * LDH + c3] : 0.f;
                    w[3][2] = (k + 4 <= hi) ? H[(k + 4) * LDH + c3] : 0.f;
                }
            }
        }
    }
    __syncthreads();

    // ---------- identify diagonal blocks ----------
    if (tid == 0) {
        int b = 0, i = 0;
        while (i < N) {
            int sz = (i < N - 1 && H[(i + 1) * LDH + i] != 0.f) ? 2 : 1;
            s_cb[b] = i; s_bsz[b] = sz;
            s_bs[i] = i; s_fbi[i] = b;
            if (sz == 2) { s_bs[i + 1] = i; s_fbi[i + 1] = b; }
            i += sz; b++;
        }
        s_nb = b;
    }
    __syncthreads();
    const int nb = s_nb;

    // ---------- amin over eigenvalue magnitudes ----------
    {
        float em = 3.4e38f;
        if (tid < nb) {
            int i = s_cb[tid];
            if (s_bsz[tid] == 1) em = fabsf(H[i * LDH + i]);
            else {
                float a=H[i*LDH+i], b=H[i*LDH+i+1], c=H[(i+1)*LDH+i], dd=H[(i+1)*LDH+i+1];
                float md=0.5f*(a-dd), disc=md*md+b*c;
                if (disc < 0.f) em = sqrtf(fmaxf(a*dd - b*c, 0.f));
                else {
                    float sq=sqrtf(disc), m2=0.5f*(a+dd);
                    em = fminf(fabsf(m2+sq), fabsf(m2-sq));
                }
            }
        }
        #pragma unroll
        for (int off = 16; off >= 1; off >>= 1) em = fminf(em, __shfl_xor_sync(0xffffffffu, em, off));
        if (lane == 0) s_red[warp] = em;
        __syncthreads();
        if (tid == 0) s_amin = fminf(fminf(s_red[0], s_red[1]), fminf(s_red[2], s_red[3]));
        __syncthreads();
    }

    // ---------- per-block F_II ----------
    if (tid < nb) {
        int i = s_cb[tid];
        float e = 1e-6f * s_amin;
        if (s_bsz[tid] == 1) s_f2[tid][0] = fabsf(H[i * LDH + i]) + e;
        else {
            float a=H[i*LDH+i], b=H[i*LDH+i+1], c=H[(i+1)*LDH+i], dd=H[(i+1)*LDH+i+1];
            float md=0.5f*(a-dd), disc=md*md+b*c, m2=0.5f*(a+dd);
            if (disc < 0.f) {
                float cc = sqrtf(fmaxf(a*dd - b*c, 0.f)) + e;
                s_f2[tid][0]=cc; s_f2[tid][1]=0.f; s_f2[tid][2]=0.f; s_f2[tid][3]=cc;
            } else {
                float sq=sqrtf(disc), l1=m2+sq, l2=m2-sq;
                float f1=fabsf(l1)+e, f2=fabsf(l2)+e, al, be;
                if (fabsf(l1-l2) > 1e-5f*(fabsf(l1)+fabsf(l2)) + 1e-30f) {
                    float idl = 1.f/(l1-l2);
                    al=(f1-f2)*idl; be=(f2*l1-f1*l2)*idl;
                } else { al=(l1>=0.f)?1.f:-1.f; be=f1-al*l1; }
                s_f2[tid][0]=al*a+be; s_f2[tid][1]=al*b; s_f2[tid][2]=al*c; s_f2[tid][3]=al*dd+be;
            }
        }
    }
    __syncthreads();

    // ---------- block Parlett: F_IJ packed at H[(iJ+c)*LDH + iI+r] ----------
    for (int pd = 1; pd < nb; pd++) {
        int I = tid, J = I + pd;
        if (J < nb) {
            int nI=s_bsz[I], nJ=s_bsz[J], iI=s_cb[I], iJ=s_cb[J];
            float TIJ[4], Rv[4]={0,0,0,0};
            for (int r=0;r<nI;r++) for (int c=0;c<nJ;c++) TIJ[r*2+c]=H[(iI+r)*LDH+iJ+c];
            for (int r=0;r<nI;r++) for (int c=0;c<nJ;c++) {
                float acc=0.f;
                for (int q=0;q<nI;q++) acc += s_f2[I][r*2+q]*TIJ[q*2+c];
                for (int q=0;q<nJ;q++) acc -= TIJ[r*2+q]*s_f2[J][q*2+c];
                Rv[r*2+c]=acc;
            }
            for (int K=I+1;K<J;K++) {
                int nK=s_bsz[K], iK=s_cb[K];
                for (int r=0;r<nI;r++) for (int c=0;c<nJ;c++) {
                    float acc=Rv[r*2+c];
                    for (int q=0;q<nK;q++)
                        acc += H[(iK+q)*LDH+iI+r]*H[(iK+q)*LDH+iJ+c]
                             - H[(iI+r)*LDH+iK+q]*H[(iJ+c)*LDH+iK+q];
                    Rv[r*2+c]=acc;
                }
            }
            float TII[4], TJJ[4];
            for (int r=0;r<nI;r++) for (int c=0;c<nI;c++) TII[r*2+c]=H[(iI+r)*LDH+iI+c];
            for (int r=0;r<nJ;r++) for (int c=0;c<nJ;c++) TJJ[r*2+c]=H[(iJ+r)*LDH+iJ+c];
            int n = nI * nJ;
            float K4[16], Xv[4];
            for (int c=0;c<nJ;c++) for (int r=0;r<nI;r++) {
                int row = r + nI*c;
                for (int c2=0;c2<nJ;c2++) for (int r2=0;r2<nI;r2++) {
                    int col = r2 + nI*c2;
                    float val = 0.f;
                    if (c == c2) val += TII[r*2+r2];
                    if (r == r2) val -= TJJ[c2*2+c];
                    K4[row*4+col] = val;
                }
                Xv[row] = Rv[r*2+c];
            }
            for (int p=0;p<n;p++) {
                int pv=p; float mx=fabsf(K4[p*4+p]);
                for (int q=p+1;q<n;q++){ float v=fabsf(K4[q*4+p]); if(v>mx){mx=v;pv=q;} }
                if (pv!=p){ for(int q=p;q<n;q++){float tmp=K4[p*4+q];K4[p*4+q]=K4[pv*4+q];K4[pv*4+q]=tmp;}
                            float tmp=Xv[p];Xv[p]=Xv[pv];Xv[pv]=tmp; }
                float ip = 1.f / guard(K4[p*4+p]);
                for (int q=p+1;q<n;q++) {
                    float fc = K4[q*4+p]*ip;
                    for (int q3=p+1;q3<n;q3++) K4[q*4+q3]-=fc*K4[p*4+q3];
                    Xv[q]-=fc*Xv[p];
                }
            }
            for (int p=n-1;p>=0;p--) {
                float acc=Xv[p];
                for (int q=p+1;q<n;q++) acc-=K4[p*4+q]*Xv[q];
                Xv[p]=acc/guard(K4[p*4+p]);
            }
            for (int c=0;c<nJ;c++) for (int r=0;r<nI;r++) H[(iJ+c)*LDH+iI+r]=Xv[r+nI*c];
        }
        __syncthreads();
    }

    // ---------- G = Q * F (2 threads per row) ----------
    {
        const int r = tid & 63, half = tid >> 6;
        float acc[32];
        for (int jj = 0; jj < 32; jj++) {
            int j = half * 32 + jj;
            int bsj = s_bs[j], b = s_fbi[j];
            float a = 0.f;
            for (int i2 = 0; i2 < bsj; i2++) a += Q[r*LDH+i2] * H[j*LDH+i2];
            if (s_bsz[b] == 1) a += Q[r*LDH+j] * s_f2[b][0];
            else {
                int loc = j - bsj;
                a += Q[r*LDH+bsj] * s_f2[b][loc] + Q[r*LDH+bsj+1] * s_f2[b][2+loc];
            }
            acc[jj] = a;
        }
        __syncthreads();
        for (int jj = 0; jj < 32; jj++) H[r*LDH + half*32 + jj] = acc[jj];
    }
    __syncthreads();

    // ---------- M = G * Q^T (2 threads per row) ----------
    {
        const int r = tid & 63, half = tid >> 6;
        float acc[32];
        for (int jj = 0; jj < 32; jj++) {
            int j = half * 32 + jj;
            float a = 0.f;
            for (int kk = 0; kk < N; kk++) a += H[r*LDH+kk] * Q[j*LDH+kk];
            acc[jj] = a;
        }
        __syncthreads();
        for (int jj = 0; jj < 32; jj++) H[r*LDH + half*32 + jj] = acc[jj];
    }
    __syncthreads();

    for (int idx = tid; idx < N * N; idx += NT) {
        int i = idx >> 6, j = idx & 63;
        Og[idx] = 0.5f * (H[i * LDH + j] + H[j * LDH + i]);
    }
}

extern "C" void kernel_launch(void* const* d_in, const int* in_sizes, int n_in,
                              void* d_out, int out_size) {
    const float* x = (const float*)d_in[0];
    float* out = (float*)d_out;
    int nmat = in_sizes[0] / (N * N);
    size_t smem = 2 * N * LDH * sizeof(float);   // 33,280 B -> 6 blocks/SM
    spd_project_kernel<<<nmat, NT, smem>>>(x, out, nmat);
}